// round 13
// baseline (speedup 1.0000x reference)
#include <cuda_runtime.h>
#include <cuda_fp16.h>
#include <cstdint>

// ---------------- problem constants ----------------
#define MAXN   200000
#define MAXE   500000
#define F_IN_  165
#define HID_   256
#define KPAD   352            // padded K (11 chunks of 32)
#define XOFF   176            // root-x slice offset within an A row
#define XH_W   176            // dense fp16 x row width (165 + 11 zero pad)
#define BK     32
#define NITER  (KPAD / BK)    // 11

// ---------------- device scratch ----------------
__device__ float g_deg[MAXN];                                // 1/max(deg,1)
__device__ __align__(16) float g_t  [MAXN * 2];
__device__ __align__(16) float g_rr [MAXN * 2];
// A row layout: [agg(0..164) | 0(165..175) | x(176..340) | 0(341..351)]
__device__ __align__(16) __half g_Ah[(size_t)MAXN * KPAD];
__device__ __align__(16) __half g_xh[(size_t)MAXN * XH_W];   // dense fp16 x (L2-resident)
__device__ __align__(16) __half g_Bh[HID_ * KPAD];
__device__ int g_ei[2 * MAXE];
__device__ int g_is64;
// CSR build
__device__ int g_cnt[MAXN];
__device__ int g_fc[MAXN];
__device__ int g_rowstart[MAXN + 1];
__device__ int g_blocksum[256];
__device__ int g_csr[MAXE];

// ---------------- PTX helpers (base-ISA; tcgen05 is sm_103a-gated, unusable here) ----------------
__device__ __forceinline__ uint32_t smem_u32(const void* p) {
    uint32_t a;
    asm("{ .reg .u64 t; cvta.to.shared.u64 t, %1; cvt.u32.u64 %0, t; }" : "=r"(a) : "l"(p));
    return a;
}
__device__ __forceinline__ void ldsm4(uint32_t& r0, uint32_t& r1, uint32_t& r2, uint32_t& r3,
                                      uint32_t addr) {
    asm volatile("ldmatrix.sync.aligned.m8n8.x4.shared.b16 {%0,%1,%2,%3}, [%4];"
                 : "=r"(r0), "=r"(r1), "=r"(r2), "=r"(r3) : "r"(addr));
}
#define MMA16816(c, a0, a1, a2, a3, b0, b1)                                            \
    asm volatile(                                                                      \
        "mma.sync.aligned.m16n8k16.row.col.f32.f16.f16.f32 "                           \
        "{%0,%1,%2,%3}, {%4,%5,%6,%7}, {%8,%9}, {%0,%1,%2,%3};"                        \
        : "+f"((c)[0]), "+f"((c)[1]), "+f"((c)[2]), "+f"((c)[3])                       \
        : "r"(a0), "r"(a1), "r"(a2), "r"(a3), "r"(b0), "r"(b1))
#define CP16(dst, src, pred)                                                           \
    asm volatile("cp.async.cg.shared.global [%0], [%1], 16, %2;"                       \
                 :: "r"(dst), "l"(src), "r"((pred) ? 16 : 0) : "memory")
#define CP_COMMIT() asm volatile("cp.async.commit_group;" ::: "memory")
#define CP_WAIT(n)  asm volatile("cp.async.wait_group %0;" :: "n"(n) : "memory")

// ---------------- edge index canon + fused dst histogram ----------------
__global__ void detect_kernel(const void* ei, int twoE) {
    const int* p = (const int*)ei;
    int nz = 0;
    for (int i = threadIdx.x; i < 256; i += 32)
        if (2 * i + 1 < twoE) nz += (p[2 * i + 1] != 0);
    #pragma unroll
    for (int o = 16; o; o >>= 1) nz += __shfl_xor_sync(0xffffffffu, nz, o);
    if (threadIdx.x == 0) g_is64 = (nz == 0) ? 1 : 0;
}
__global__ void convert_hist_kernel(const void* ei, int twoE) {
    int is64 = g_is64;
    int E = twoE / 2;
    const long long* p64 = (const long long*)ei;
    const int* p32 = (const int*)ei;
    for (int i = blockIdx.x * blockDim.x + threadIdx.x; i < twoE; i += gridDim.x * blockDim.x) {
        int v = is64 ? (int)p64[i] : p32[i];
        g_ei[i] = v;
        if (i >= E) atomicAdd(&g_cnt[v], 1);
    }
}

// ---------------- small zero ----------------
__global__ void zero_small_kernel(int N) {
    int i = blockIdx.x * blockDim.x + threadIdx.x;
    if (i < N) { g_cnt[i] = 0; g_fc[i] = 0; }
    if (i < 2 * N) { g_t[i] = 0.f; g_rr[i] = 0.f; }
}

// ---------------- x -> dense fp16 rows (88 half2 per row) ----------------
__global__ void convert_x_kernel(const float* __restrict__ x, int N) {
    int u = blockIdx.x * blockDim.x + threadIdx.x;
    if (u >= N * (XH_W / 2)) return;
    int row = u / (XH_W / 2), j = u % (XH_W / 2);
    int k = 2 * j;
    const float* xr = x + (size_t)row * F_IN_;
    float v0 = (k < F_IN_)     ? xr[k]     : 0.f;
    float v1 = (k + 1 < F_IN_) ? xr[k + 1] : 0.f;
    ((__half2*)(g_xh + (size_t)row * XH_W))[j] = __float22half2_rn(make_float2(v0, v1));
}

// ---------------- CSR build: scan -> fill ----------------
#define SCAN_T 256
#define SCAN_E 1024
__global__ void scan1_kernel(int N) {
    __shared__ int ts[SCAN_T];
    int b = blockIdx.x, t = threadIdx.x;
    int base = b * SCAN_E + t * 4;
    int v[4];
    #pragma unroll
    for (int j = 0; j < 4; j++) v[j] = (base + j < N) ? g_cnt[base + j] : 0;
    int s = v[0] + v[1] + v[2] + v[3];
    ts[t] = s;
    __syncthreads();
    for (int o = 1; o < SCAN_T; o <<= 1) {
        int xv = (t >= o) ? ts[t - o] : 0;
        __syncthreads();
        ts[t] += xv;
        __syncthreads();
    }
    if (t == SCAN_T - 1) g_blocksum[b] = ts[t];
    int run = ts[t] - s;   // exclusive
    #pragma unroll
    for (int j = 0; j < 4; j++) {
        if (base + j < N) g_rowstart[base + j] = run;
        run += v[j];
    }
}
__global__ void scan2_kernel(int nb) {
    __shared__ int ts[256];
    int t = threadIdx.x;
    ts[t] = (t < nb) ? g_blocksum[t] : 0;
    __syncthreads();
    int s = ts[t];
    for (int o = 1; o < 256; o <<= 1) {
        int xv = (t >= o) ? ts[t - o] : 0;
        __syncthreads();
        ts[t] += xv;
        __syncthreads();
    }
    g_blocksum[t] = ts[t] - s;   // exclusive
}
__global__ void scan3_kernel(int N, int E) {
    int i = blockIdx.x * blockDim.x + threadIdx.x;
    if (i < N) g_rowstart[i] += g_blocksum[i / SCAN_E];
    if (i == 0) g_rowstart[N] = E;
}
__global__ void fill_kernel(int E) {
    int e = blockIdx.x * blockDim.x + threadIdx.x;
    if (e >= E) return;
    int s = g_ei[e], d = g_ei[E + e];
    int pos = g_rowstart[d] + atomicAdd(&g_fc[d], 1);
    g_csr[pos] = s;
}

// ---------------- layer-1 aggregation: fp16 gather (L2-resident), full-lane half2 ----------------
__global__ void aggregate_kernel(int N) {
    int warp = (blockIdx.x * blockDim.x + threadIdx.x) >> 5;
    int lane = threadIdx.x & 31;
    if (warp >= N) return;
    int start = g_rowstart[warp], end = g_rowstart[warp + 1];
    float f0 = 0.f, f1 = 0.f, f2 = 0.f, f3 = 0.f, f4 = 0.f, f5 = 0.f;
    const bool tail = lane < 24;
    int j = start;
    for (; j + 1 < end; j += 2) {            // 2-neighbor unroll for load MLP
        const __half2* a = (const __half2*)(g_xh + (size_t)g_csr[j] * XH_W);
        const __half2* b = (const __half2*)(g_xh + (size_t)g_csr[j + 1] * XH_W);
        float2 p0 = __half22float2(a[lane]),      q0 = __half22float2(b[lane]);
        float2 p1 = __half22float2(a[lane + 32]), q1 = __half22float2(b[lane + 32]);
        f0 += p0.x + q0.x; f1 += p0.y + q0.y;
        f2 += p1.x + q1.x; f3 += p1.y + q1.y;
        if (tail) {
            float2 p2 = __half22float2(a[lane + 64]), q2 = __half22float2(b[lane + 64]);
            f4 += p2.x + q2.x; f5 += p2.y + q2.y;
        }
    }
    if (j < end) {
        const __half2* a = (const __half2*)(g_xh + (size_t)g_csr[j] * XH_W);
        float2 p0 = __half22float2(a[lane]);
        float2 p1 = __half22float2(a[lane + 32]);
        f0 += p0.x; f1 += p0.y; f2 += p1.x; f3 += p1.y;
        if (tail) {
            float2 p2 = __half22float2(a[lane + 64]);
            f4 += p2.x; f5 += p2.y;
        }
    }
    float inv = 1.0f / fmaxf((float)(end - start), 1.0f);
    __half2* ar = (__half2*)(g_Ah + (size_t)warp * KPAD);
    const __half2* xr = (const __half2*)(g_xh + (size_t)warp * XH_W);
    ar[lane]      = __float22half2_rn(make_float2(f0 * inv, f1 * inv));
    ar[lane + 32] = __float22half2_rn(make_float2(f2 * inv, f3 * inv));
    if (tail) ar[lane + 64] = __float22half2_rn(make_float2(f4 * inv, f5 * inv));
    // root slice: straight copy of the dense fp16 row (includes its zero pad)
    ar[88 + lane]      = xr[lane];
    ar[88 + lane + 32] = xr[lane + 32];
    if (tail) ar[88 + lane + 64] = xr[lane + 64];
    if (lane == 0) g_deg[warp] = inv;
}

// ---------------- B fp16 prep (layout matches A: w1l at 0, w1r at XOFF) ----------------
__global__ void prep_B_kernel(const float* __restrict__ w1l, const float* __restrict__ w1r) {
    int u = blockIdx.x * blockDim.x + threadIdx.x;
    if (u >= HID_ * (KPAD / 8)) return;
    int n = u / (KPAD / 8);
    int kb = (u % (KPAD / 8)) * 8;
    __align__(16) __half h[8];
    #pragma unroll
    for (int j = 0; j < 8; j++) {
        int k = kb + j;
        float v = 0.f;
        if (k < F_IN_)                          v = w1l[k * HID_ + n];
        else if (k >= XOFF && k < XOFF + F_IN_) v = w1r[(k - XOFF) * HID_ + n];
        h[j] = __float2half(v);
    }
    *(uint4*)(g_Bh + (size_t)n * KPAD + kb) = *(const uint4*)h;
}

// ---------------- fp16 mma.sync GEMM: 64x256 tile, 8 warps (2Mx4N), 2 CTAs/SM (R9/R12 best) ----------------
#define BM     64
#define ROWB   80
#define SA_SZ  (BM * ROWB)            // 5120
#define SB_SZ  (256 * ROWB)           // 20480
#define OFF_AS(st) ((st) * SA_SZ)                 // A per stage
#define OFF_BS(st) (2 * SA_SZ + (st) * SB_SZ)     // B per stage
#define OFF_TAB    (2 * SA_SZ + 2 * SB_SZ)        // 51200
#define SMEM_DYN   (OFF_TAB + 1024 + 2048 + 2048) // 56320

__global__ __launch_bounds__(256, 2) void gemm_tc_kernel(
    const float* __restrict__ b1, const float* __restrict__ w2l,
    const float* __restrict__ w2r, int N)
{
    extern __shared__ __align__(16) char sm[];
    uint32_t sb = smem_u32(sm);
    float* b1s  = (float*)(sm + OFF_TAB);
    float* w2ls = (float*)(sm + OFF_TAB + 1024);
    float* w2rs = (float*)(sm + OFF_TAB + 1024 + 2048);

    const int tid  = threadIdx.x;
    const int wid  = tid >> 5;
    const int lane = tid & 31;
    const int wm   = wid >> 2;          // 0..1 (32 rows each)
    const int wn   = wid & 3;           // 0..3 (64 cols each)
    const size_t rowbase = (size_t)blockIdx.x * BM;

    for (int i = tid; i < HID_; i += 256) b1s[i] = b1[i];
    for (int i = tid; i < HID_ * 2; i += 256) { w2ls[i] = w2l[i]; w2rs[i] = w2r[i]; }

    float acc[2][8][4];
    #pragma unroll
    for (int a = 0; a < 2; a++)
        #pragma unroll
        for (int b = 0; b < 8; b++)
            #pragma unroll
            for (int c = 0; c < 4; c++) acc[a][b][c] = 0.f;

    auto load_stage = [&](int kt, int buf) {
        {
            int r = tid >> 2, u = tid & 3;
            uint32_t so = sb + OFF_AS(buf) + r * ROWB + u * 16;
            size_t row = rowbase + r;
            CP16(so, g_Ah + row * KPAD + kt * BK + u * 8, row < (size_t)N);
        }
        #pragma unroll
        for (int j = 0; j < 4; j++) {
            int cid = tid + 256 * j;
            int r = cid >> 2, u = cid & 3;
            uint32_t so = sb + OFF_BS(buf) + r * ROWB + u * 16;
            CP16(so, g_Bh + (size_t)r * KPAD + kt * BK + u * 8, 1);
        }
        CP_COMMIT();
    };

    load_stage(0, 0);

    for (int kt = 0; kt < NITER; kt++) {
        int buf = kt & 1;
        if (kt + 1 < NITER) {
            load_stage(kt + 1, buf ^ 1);
            CP_WAIT(1);
        } else {
            CP_WAIT(0);
        }
        __syncthreads();

        uint32_t sA = sb + OFF_AS(buf);
        uint32_t sB = sb + OFF_BS(buf);
        #pragma unroll
        for (int ks = 0; ks < 2; ks++) {
            uint32_t bh[4][4];
            #pragma unroll
            for (int nf = 0; nf < 4; nf++) {
                int brow  = wn * 64 + nf * 16 + (lane & 7) + ((lane >> 4) << 3);
                int bunit = ks * 2 + ((lane >> 3) & 1);
                ldsm4(bh[nf][0], bh[nf][1], bh[nf][2], bh[nf][3],
                      sB + brow * ROWB + bunit * 16);
            }
            #pragma unroll
            for (int mf = 0; mf < 2; mf++) {
                int arow  = wm * 32 + mf * 16 + (lane & 15);
                int aunit = ks * 2 + (lane >> 4);
                uint32_t ah0, ah1, ah2, ah3;
                ldsm4(ah0, ah1, ah2, ah3, sA + arow * ROWB + aunit * 16);
                #pragma unroll
                for (int nf8 = 0; nf8 < 8; nf8++) {
                    int nf = nf8 >> 1, hf = nf8 & 1;
                    MMA16816(acc[mf][nf8], ah0, ah1, ah2, ah3,
                             bh[nf][hf * 2], bh[nf][hf * 2 + 1]);
                }
            }
        }
        __syncthreads();
    }

    // ---- fused epilogue: relu(acc+b1) then partial dot with w2l/w2r ----
    float pt0[4], pt1[4], pr0[4], pr1[4];
    #pragma unroll
    for (int i = 0; i < 4; i++) { pt0[i] = pt1[i] = pr0[i] = pr1[i] = 0.f; }

    #pragma unroll
    for (int mf = 0; mf < 2; mf++) {
        #pragma unroll
        for (int nf8 = 0; nf8 < 8; nf8++) {
            #pragma unroll
            for (int j = 0; j < 4; j++) {
                int colL = wn * 64 + nf8 * 8 + 2 * (lane & 3) + (j & 1);
                int i4 = mf * 2 + (j >> 1);
                float h = fmaxf(acc[mf][nf8][j] + b1s[colL], 0.f);
                pt0[i4] += h * w2ls[colL * 2];
                pt1[i4] += h * w2ls[colL * 2 + 1];
                pr0[i4] += h * w2rs[colL * 2];
                pr1[i4] += h * w2rs[colL * 2 + 1];
            }
        }
    }
    #pragma unroll
    for (int i = 0; i < 4; i++) {
        #pragma unroll
        for (int o = 1; o <= 2; o <<= 1) {
            pt0[i] += __shfl_xor_sync(0xffffffffu, pt0[i], o);
            pt1[i] += __shfl_xor_sync(0xffffffffu, pt1[i], o);
            pr0[i] += __shfl_xor_sync(0xffffffffu, pr0[i], o);
            pr1[i] += __shfl_xor_sync(0xffffffffu, pr1[i], o);
        }
        if ((lane & 3) == 0) {
            size_t row = rowbase + wm * 32 + (i >> 1) * 16 + (lane >> 2) + (i & 1) * 8;
            if (row < (size_t)N) {
                asm volatile("red.global.add.v2.f32 [%0], {%1, %2};"
                             :: "l"(&g_t[row * 2]), "f"(pt0[i]), "f"(pt1[i]) : "memory");
                asm volatile("red.global.add.v2.f32 [%0], {%1, %2};"
                             :: "l"(&g_rr[row * 2]), "f"(pr0[i]), "f"(pr1[i]) : "memory");
            }
        }
    }
}

// ---------------- layer-2 gather (CSR, thread-per-node) fused with finalize ----------------
__global__ void gather2_kernel(float* __restrict__ out, const float* __restrict__ b2, int N) {
    int i = blockIdx.x * blockDim.x + threadIdx.x;
    if (i >= N) return;
    int start = g_rowstart[i], end = g_rowstart[i + 1];
    float s0 = 0.f, s1 = 0.f;
    for (int j = start; j < end; j++) {
        int s = g_csr[j];
        float2 v = *(const float2*)&g_t[s * 2];
        s0 += v.x;
        s1 += v.y;
    }
    float inv = g_deg[i];
    out[i * 2]     = s0 * inv + g_rr[i * 2]     + __ldg(&b2[0]);
    out[i * 2 + 1] = s1 * inv + g_rr[i * 2 + 1] + __ldg(&b2[1]);
}

// ---------------- edge_index passthrough ----------------
__global__ void ei_out_f32_kernel(float* out, int twoE) {
    int i = blockIdx.x * blockDim.x + threadIdx.x;
    if (i < twoE) out[i] = (float)g_ei[i];
}
__global__ void ei_out_i64_kernel(long long* out, int twoE) {
    int i = blockIdx.x * blockDim.x + threadIdx.x;
    if (i < twoE) out[i] = (long long)g_ei[i];
}

// ---------------- launch ----------------
extern "C" void kernel_launch(void* const* d_in, const int* in_sizes, int n_in,
                              void* d_out, int out_size) {
    const float* x   = (const float*)d_in[0];
    const void*  ei  = d_in[1];
    const float* w1l = (const float*)d_in[2];
    const float* w1r = (const float*)d_in[3];
    const float* b1  = (const float*)d_in[4];
    const float* w2l = (const float*)d_in[5];
    const float* w2r = (const float*)d_in[6];
    const float* b2  = (const float*)d_in[7];

    int N = in_sizes[0] / F_IN_;
    int twoE = in_sizes[1];
    int E = twoE / 2;
    float* out = (float*)d_out;

    cudaFuncSetAttribute(gemm_tc_kernel, cudaFuncAttributeMaxDynamicSharedMemorySize, SMEM_DYN);

    zero_small_kernel<<<(2 * N + 255) / 256, 256>>>(N);
    detect_kernel<<<1, 32>>>(ei, twoE);
    convert_hist_kernel<<<1024, 256>>>(ei, twoE);
    convert_x_kernel<<<(N * (XH_W / 2) + 255) / 256, 256>>>(x, N);
    int nsb = (N + SCAN_E - 1) / SCAN_E;
    scan1_kernel<<<nsb, SCAN_T>>>(N);
    scan2_kernel<<<1, 256>>>(nsb);
    scan3_kernel<<<(N + 255) / 256, 256>>>(N, E);
    fill_kernel<<<(E + 255) / 256, 256>>>(E);
    aggregate_kernel<<<(N * 32 + 255) / 256, 256>>>(N);
    prep_B_kernel<<<(HID_ * (KPAD / 8) + 255) / 256, 256>>>(w1l, w1r);
    gemm_tc_kernel<<<(N + BM - 1) / BM, 256, SMEM_DYN>>>(b1, w2l, w2r, N);
    gather2_kernel<<<(N + 255) / 256, 256>>>(out, b2, N);

    long long rem = (long long)out_size - (long long)2 * N;
    if (rem >= (long long)twoE) {
        if (rem >= 2LL * twoE)
            ei_out_i64_kernel<<<(twoE + 255) / 256, 256>>>((long long*)(out + (size_t)2 * N), twoE);
        else
            ei_out_f32_kernel<<<(twoE + 255) / 256, 256>>>(out + (size_t)2 * N, twoE);
    }
}

// round 14
// speedup vs baseline: 1.2387x; 1.2387x over previous
#include <cuda_runtime.h>
#include <cuda_fp16.h>
#include <cstdint>

// ---------------- problem constants ----------------
#define MAXN   200000
#define MAXE   500000
#define F_IN_  165
#define HID_   256
#define KTOT   330
#define KPAD   352            // padded K (11 chunks of 32)
#define BK     32
#define NITER  (KPAD / BK)    // 11

// ---------------- device scratch ----------------
__device__ float g_deg[MAXN];                                // 1/max(deg,1)
__device__ __align__(16) float g_t  [MAXN * 2];
__device__ __align__(16) float g_rr [MAXN * 2];
__device__ __align__(16) __half g_Ah[(size_t)MAXN * KPAD];   // [agg*invd | x | pad] fp16
__device__ __align__(16) __half g_Bh[HID_ * KPAD];           // [w1_l ; w1_r] fp16
__device__ int g_ei[2 * MAXE];
__device__ int g_is64;
// CSR build
__device__ int g_cnt[MAXN];
__device__ int g_fc[MAXN];
__device__ int g_rowstart[MAXN + 1];
__device__ int g_blocksum[256];
__device__ int g_csr[MAXE];

// ---------------- PTX helpers (base-ISA; tcgen05 is sm_103a-gated, unusable here) ----------------
__device__ __forceinline__ uint32_t smem_u32(const void* p) {
    uint32_t a;
    asm("{ .reg .u64 t; cvta.to.shared.u64 t, %1; cvt.u32.u64 %0, t; }" : "=r"(a) : "l"(p));
    return a;
}
__device__ __forceinline__ void ldsm4(uint32_t& r0, uint32_t& r1, uint32_t& r2, uint32_t& r3,
                                      uint32_t addr) {
    asm volatile("ldmatrix.sync.aligned.m8n8.x4.shared.b16 {%0,%1,%2,%3}, [%4];"
                 : "=r"(r0), "=r"(r1), "=r"(r2), "=r"(r3) : "r"(addr));
}
#define MMA16816(c, a0, a1, a2, a3, b0, b1)                                            \
    asm volatile(                                                                      \
        "mma.sync.aligned.m16n8k16.row.col.f32.f16.f16.f32 "                           \
        "{%0,%1,%2,%3}, {%4,%5,%6,%7}, {%8,%9}, {%0,%1,%2,%3};"                        \
        : "+f"((c)[0]), "+f"((c)[1]), "+f"((c)[2]), "+f"((c)[3])                       \
        : "r"(a0), "r"(a1), "r"(a2), "r"(a3), "r"(b0), "r"(b1))
#define CP16(dst, src, pred)                                                           \
    asm volatile("cp.async.cg.shared.global [%0], [%1], 16, %2;"                       \
                 :: "r"(dst), "l"(src), "r"((pred) ? 16 : 0) : "memory")
#define CP_COMMIT() asm volatile("cp.async.commit_group;" ::: "memory")
#define CP_WAIT(n)  asm volatile("cp.async.wait_group %0;" :: "n"(n) : "memory")

// ---------------- edge index canon + fused dst histogram ----------------
__global__ void detect_kernel(const void* ei, int twoE) {
    const int* p = (const int*)ei;
    int nz = 0;
    for (int i = threadIdx.x; i < 256; i += 32)
        if (2 * i + 1 < twoE) nz += (p[2 * i + 1] != 0);
    #pragma unroll
    for (int o = 16; o; o >>= 1) nz += __shfl_xor_sync(0xffffffffu, nz, o);
    if (threadIdx.x == 0) g_is64 = (nz == 0) ? 1 : 0;
}
__global__ void convert_hist_kernel(const void* ei, int twoE) {
    int is64 = g_is64;
    int E = twoE / 2;
    const long long* p64 = (const long long*)ei;
    const int* p32 = (const int*)ei;
    for (int i = blockIdx.x * blockDim.x + threadIdx.x; i < twoE; i += gridDim.x * blockDim.x) {
        int v = is64 ? (int)p64[i] : p32[i];
        g_ei[i] = v;
        if (i >= E) atomicAdd(&g_cnt[v], 1);
    }
}

// ---------------- small zero ----------------
__global__ void zero_small_kernel(int N) {
    int i = blockIdx.x * blockDim.x + threadIdx.x;
    if (i < N) { g_cnt[i] = 0; g_fc[i] = 0; }
    if (i < 2 * N) { g_t[i] = 0.f; g_rr[i] = 0.f; }
}

// ---------------- CSR build: scan -> fill ----------------
#define SCAN_T 256
#define SCAN_E 1024
__global__ void scan1_kernel(int N) {
    __shared__ int ts[SCAN_T];
    int b = blockIdx.x, t = threadIdx.x;
    int base = b * SCAN_E + t * 4;
    int v[4];
    #pragma unroll
    for (int j = 0; j < 4; j++) v[j] = (base + j < N) ? g_cnt[base + j] : 0;
    int s = v[0] + v[1] + v[2] + v[3];
    ts[t] = s;
    __syncthreads();
    for (int o = 1; o < SCAN_T; o <<= 1) {
        int xv = (t >= o) ? ts[t - o] : 0;
        __syncthreads();
        ts[t] += xv;
        __syncthreads();
    }
    if (t == SCAN_T - 1) g_blocksum[b] = ts[t];
    int run = ts[t] - s;   // exclusive
    #pragma unroll
    for (int j = 0; j < 4; j++) {
        if (base + j < N) g_rowstart[base + j] = run;
        run += v[j];
    }
}
__global__ void scan2_kernel(int nb) {
    __shared__ int ts[256];
    int t = threadIdx.x;
    ts[t] = (t < nb) ? g_blocksum[t] : 0;
    __syncthreads();
    int s = ts[t];
    for (int o = 1; o < 256; o <<= 1) {
        int xv = (t >= o) ? ts[t - o] : 0;
        __syncthreads();
        ts[t] += xv;
        __syncthreads();
    }
    g_blocksum[t] = ts[t] - s;   // exclusive
}
__global__ void scan3_kernel(int N, int E) {
    int i = blockIdx.x * blockDim.x + threadIdx.x;
    if (i < N) g_rowstart[i] += g_blocksum[i / SCAN_E];
    if (i == 0) g_rowstart[N] = E;
}
__global__ void fill_kernel(int E) {
    int e = blockIdx.x * blockDim.x + threadIdx.x;
    if (e >= E) return;
    int s = g_ei[e], d = g_ei[E + e];
    int pos = g_rowstart[d] + atomicAdd(&g_fc[d], 1);
    g_csr[pos] = s;
}

// ---------------- layer-1 aggregation + fp16 A materialization (R12 proven) ----------------
__global__ void aggregate_kernel(const float* __restrict__ x, int N) {
    int warp = (blockIdx.x * blockDim.x + threadIdx.x) >> 5;
    int lane = threadIdx.x & 31;
    if (warp >= N) return;
    int start = g_rowstart[warp], end = g_rowstart[warp + 1];
    float acc[6] = {0.f, 0.f, 0.f, 0.f, 0.f, 0.f};
    int j = start;
    for (; j + 1 < end; j += 2) {           // 2-neighbor unroll for load MLP
        int s0 = g_csr[j], s1 = g_csr[j + 1];
        const float* xs0 = x + (size_t)s0 * F_IN_;
        const float* xs1 = x + (size_t)s1 * F_IN_;
        #pragma unroll
        for (int m = 0; m < 6; m++) {
            int k = lane + 32 * m;
            if (k < F_IN_) acc[m] += xs0[k] + xs1[k];
        }
    }
    if (j < end) {
        int s = g_csr[j];
        const float* xs = x + (size_t)s * F_IN_;
        #pragma unroll
        for (int m = 0; m < 6; m++) {
            int k = lane + 32 * m;
            if (k < F_IN_) acc[m] += xs[k];
        }
    }
    float inv = 1.0f / fmaxf((float)(end - start), 1.0f);
    __half* ar = g_Ah + (size_t)warp * KPAD;
    const float* xr = x + (size_t)warp * F_IN_;
    #pragma unroll
    for (int m = 0; m < 6; m++) {
        int k = lane + 32 * m;
        if (k < F_IN_) {
            ar[k] = __float2half(acc[m] * inv);
            ar[F_IN_ + k] = __float2half(xr[k]);
        }
    }
    if (lane < KPAD - KTOT) ar[KTOT + lane] = __float2half(0.f);
    if (lane == 0) g_deg[warp] = inv;
}

// ---------------- B fp16 prep ----------------
__global__ void prep_B_kernel(const float* __restrict__ w1l, const float* __restrict__ w1r) {
    int u = blockIdx.x * blockDim.x + threadIdx.x;
    if (u >= HID_ * (KPAD / 8)) return;
    int n = u / (KPAD / 8);
    int kb = (u % (KPAD / 8)) * 8;
    __align__(16) __half h[8];
    #pragma unroll
    for (int j = 0; j < 8; j++) {
        int k = kb + j;
        float v = 0.f;
        if (k < F_IN_)      v = w1l[k * HID_ + n];
        else if (k < KTOT)  v = w1r[(k - F_IN_) * HID_ + n];
        h[j] = __float2half(v);
    }
    *(uint4*)(g_Bh + (size_t)n * KPAD + kb) = *(const uint4*)h;
}

// ---------------- fp16 mma.sync GEMM: 64x256, 8 warps, 2 CTAs/SM, 3-stage single-sync ----------------
#define BM     64
#define ROWB   80
#define SA_SZ  (BM * ROWB)            // 5120
#define SB_SZ  (256 * ROWB)           // 20480
#define STG_SZ (SA_SZ + SB_SZ)        // 25600
#define OFF_A(st) ((st) * STG_SZ)
#define OFF_B(st) ((st) * STG_SZ + SA_SZ)
#define OFF_TAB   (3 * STG_SZ)        // 76800
#define SMEM_DYN  (OFF_TAB + 1024 + 2048 + 2048)   // 81920 (x2 CTAs = 160KB/SM, fits)

__global__ __launch_bounds__(256, 2) void gemm_tc_kernel(
    const float* __restrict__ b1, const float* __restrict__ w2l,
    const float* __restrict__ w2r, int N)
{
    extern __shared__ __align__(16) char sm[];
    uint32_t sb = smem_u32(sm);
    float* b1s  = (float*)(sm + OFF_TAB);
    float* w2ls = (float*)(sm + OFF_TAB + 1024);
    float* w2rs = (float*)(sm + OFF_TAB + 1024 + 2048);

    const int tid  = threadIdx.x;
    const int wid  = tid >> 5;
    const int lane = tid & 31;
    const int wm   = wid >> 2;          // 0..1 (32 rows each)
    const int wn   = wid & 3;           // 0..3 (64 cols each)
    const size_t rowbase = (size_t)blockIdx.x * BM;

    for (int i = tid; i < HID_; i += 256) b1s[i] = b1[i];
    for (int i = tid; i < HID_ * 2; i += 256) { w2ls[i] = w2l[i]; w2rs[i] = w2r[i]; }

    float acc[2][8][4];
    #pragma unroll
    for (int a = 0; a < 2; a++)
        #pragma unroll
        for (int b = 0; b < 8; b++)
            #pragma unroll
            for (int c = 0; c < 4; c++) acc[a][b][c] = 0.f;

    auto load_stage = [&](int kt, int buf) {
        {
            int r = tid >> 2, u = tid & 3;
            uint32_t so = sb + OFF_A(buf) + r * ROWB + u * 16;
            size_t row = rowbase + r;
            CP16(so, g_Ah + row * KPAD + kt * BK + u * 8, row < (size_t)N);
        }
        #pragma unroll
        for (int j = 0; j < 4; j++) {
            int cid = tid + 256 * j;
            int r = cid >> 2, u = cid & 3;
            uint32_t so = sb + OFF_B(buf) + r * ROWB + u * 16;
            CP16(so, g_Bh + (size_t)r * KPAD + kt * BK + u * 8, 1);
        }
        CP_COMMIT();
    };

    load_stage(0, 0);
    load_stage(1, 1);

    for (int kt = 0; kt < NITER; kt++) {
        int buf = kt % 3;
        if (kt == NITER - 1) CP_WAIT(0); else CP_WAIT(1);
        __syncthreads();
        // issue next-next stage AFTER the sync: its buffer (kt+2)%3 was last read
        // at iteration kt-1, which all threads completed before this barrier.
        if (kt + 2 < NITER) load_stage(kt + 2, (kt + 2) % 3);

        uint32_t sA = sb + OFF_A(buf);
        uint32_t sB = sb + OFF_B(buf);
        #pragma unroll
        for (int ks = 0; ks < 2; ks++) {
            uint32_t bh[4][4];
            #pragma unroll
            for (int nf = 0; nf < 4; nf++) {
                int brow  = wn * 64 + nf * 16 + (lane & 7) + ((lane >> 4) << 3);
                int bunit = ks * 2 + ((lane >> 3) & 1);
                ldsm4(bh[nf][0], bh[nf][1], bh[nf][2], bh[nf][3],
                      sB + brow * ROWB + bunit * 16);
            }
            #pragma unroll
            for (int mf = 0; mf < 2; mf++) {
                int arow  = wm * 32 + mf * 16 + (lane & 15);
                int aunit = ks * 2 + (lane >> 4);
                uint32_t ah0, ah1, ah2, ah3;
                ldsm4(ah0, ah1, ah2, ah3, sA + arow * ROWB + aunit * 16);
                #pragma unroll
                for (int nf8 = 0; nf8 < 8; nf8++) {
                    int nf = nf8 >> 1, hf = nf8 & 1;
                    MMA16816(acc[mf][nf8], ah0, ah1, ah2, ah3,
                             bh[nf][hf * 2], bh[nf][hf * 2 + 1]);
                }
            }
        }
    }

    // ---- fused epilogue: relu(acc+b1) then partial dot with w2l/w2r ----
    float pt0[4], pt1[4], pr0[4], pr1[4];
    #pragma unroll
    for (int i = 0; i < 4; i++) { pt0[i] = pt1[i] = pr0[i] = pr1[i] = 0.f; }

    #pragma unroll
    for (int mf = 0; mf < 2; mf++) {
        #pragma unroll
        for (int nf8 = 0; nf8 < 8; nf8++) {
            #pragma unroll
            for (int j = 0; j < 4; j++) {
                int colL = wn * 64 + nf8 * 8 + 2 * (lane & 3) + (j & 1);
                int i4 = mf * 2 + (j >> 1);
                float h = fmaxf(acc[mf][nf8][j] + b1s[colL], 0.f);
                pt0[i4] += h * w2ls[colL * 2];
                pt1[i4] += h * w2ls[colL * 2 + 1];
                pr0[i4] += h * w2rs[colL * 2];
                pr1[i4] += h * w2rs[colL * 2 + 1];
            }
        }
    }
    #pragma unroll
    for (int i = 0; i < 4; i++) {
        #pragma unroll
        for (int o = 1; o <= 2; o <<= 1) {
            pt0[i] += __shfl_xor_sync(0xffffffffu, pt0[i], o);
            pt1[i] += __shfl_xor_sync(0xffffffffu, pt1[i], o);
            pr0[i] += __shfl_xor_sync(0xffffffffu, pr0[i], o);
            pr1[i] += __shfl_xor_sync(0xffffffffu, pr1[i], o);
        }
        if ((lane & 3) == 0) {
            size_t row = rowbase + wm * 32 + (i >> 1) * 16 + (lane >> 2) + (i & 1) * 8;
            if (row < (size_t)N) {
                asm volatile("red.global.add.v2.f32 [%0], {%1, %2};"
                             :: "l"(&g_t[row * 2]), "f"(pt0[i]), "f"(pt1[i]) : "memory");
                asm volatile("red.global.add.v2.f32 [%0], {%1, %2};"
                             :: "l"(&g_rr[row * 2]), "f"(pr0[i]), "f"(pr1[i]) : "memory");
            }
        }
    }
}

// ---------------- layer-2 gather (CSR, thread-per-node) fused with finalize ----------------
__global__ void gather2_kernel(float* __restrict__ out, const float* __restrict__ b2, int N) {
    int i = blockIdx.x * blockDim.x + threadIdx.x;
    if (i >= N) return;
    int start = g_rowstart[i], end = g_rowstart[i + 1];
    float s0 = 0.f, s1 = 0.f;
    for (int j = start; j < end; j++) {
        int s = g_csr[j];
        float2 v = *(const float2*)&g_t[s * 2];
        s0 += v.x;
        s1 += v.y;
    }
    float inv = g_deg[i];
    out[i * 2]     = s0 * inv + g_rr[i * 2]     + __ldg(&b2[0]);
    out[i * 2 + 1] = s1 * inv + g_rr[i * 2 + 1] + __ldg(&b2[1]);
}

// ---------------- edge_index passthrough ----------------
__global__ void ei_out_f32_kernel(float* out, int twoE) {
    int i = blockIdx.x * blockDim.x + threadIdx.x;
    if (i < twoE) out[i] = (float)g_ei[i];
}
__global__ void ei_out_i64_kernel(long long* out, int twoE) {
    int i = blockIdx.x * blockDim.x + threadIdx.x;
    if (i < twoE) out[i] = (long long)g_ei[i];
}

// ---------------- launch ----------------
extern "C" void kernel_launch(void* const* d_in, const int* in_sizes, int n_in,
                              void* d_out, int out_size) {
    const float* x   = (const float*)d_in[0];
    const void*  ei  = d_in[1];
    const float* w1l = (const float*)d_in[2];
    const float* w1r = (const float*)d_in[3];
    const float* b1  = (const float*)d_in[4];
    const float* w2l = (const float*)d_in[5];
    const float* w2r = (const float*)d_in[6];
    const float* b2  = (const float*)d_in[7];

    int N = in_sizes[0] / F_IN_;
    int twoE = in_sizes[1];
    int E = twoE / 2;
    float* out = (float*)d_out;

    cudaFuncSetAttribute(gemm_tc_kernel, cudaFuncAttributeMaxDynamicSharedMemorySize, SMEM_DYN);

    zero_small_kernel<<<(2 * N + 255) / 256, 256>>>(N);
    detect_kernel<<<1, 32>>>(ei, twoE);
    convert_hist_kernel<<<1024, 256>>>(ei, twoE);
    int nsb = (N + SCAN_E - 1) / SCAN_E;
    scan1_kernel<<<nsb, SCAN_T>>>(N);
    scan2_kernel<<<1, 256>>>(nsb);
    scan3_kernel<<<(N + 255) / 256, 256>>>(N, E);
    fill_kernel<<<(E + 255) / 256, 256>>>(E);
    aggregate_kernel<<<(N * 32 + 255) / 256, 256>>>(x, N);
    prep_B_kernel<<<(HID_ * (KPAD / 8) + 255) / 256, 256>>>(w1l, w1r);
    gemm_tc_kernel<<<(N + BM - 1) / BM, 256, SMEM_DYN>>>(b1, w2l, w2r, N);
    gather2_kernel<<<(N + 255) / 256, 256>>>(out, b2, N);

    long long rem = (long long)out_size - (long long)2 * N;
    if (rem >= (long long)twoE) {
        if (rem >= 2LL * twoE)
            ei_out_i64_kernel<<<(twoE + 255) / 256, 256>>>((long long*)(out + (size_t)2 * N), twoE);
        else
            ei_out_f32_kernel<<<(twoE + 255) / 256, 256>>>(out + (size_t)2 * N, twoE);
    }
}

// round 15
// speedup vs baseline: 1.2493x; 1.0086x over previous
#include <cuda_runtime.h>
#include <cuda_fp16.h>
#include <cstdint>

// ---------------- problem constants ----------------
#define MAXN   200000
#define MAXE   500000
#define F_IN_  165
#define HID_   256
#define KTOT   330
#define KPAD   352            // padded K (11 chunks of 32)
#define BK     32
#define NITER  (KPAD / BK)    // 11

// ---------------- device scratch ----------------
__device__ float g_deg[MAXN];                                // 1/max(deg,1)
__device__ __align__(16) float g_t  [MAXN * 2];
__device__ __align__(16) float g_rr [MAXN * 2];
__device__ __align__(16) __half g_Ah[(size_t)MAXN * KPAD];   // [agg*invd | x | pad] fp16
__device__ __align__(16) __half g_Bh[HID_ * KPAD];           // [w1_l ; w1_r] fp16
__device__ int g_ei[2 * MAXE];
// CSR build
__device__ int g_cnt[MAXN];
__device__ int g_fc[MAXN];
__device__ int g_rowstart[MAXN + 1];   // pre-blocksum partial scan
__device__ int g_blocksum[256];
__device__ int g_csr[MAXE];

// ---------------- PTX helpers (base-ISA; tcgen05 is sm_103a-gated, unusable here) ----------------
__device__ __forceinline__ uint32_t smem_u32(const void* p) {
    uint32_t a;
    asm("{ .reg .u64 t; cvta.to.shared.u64 t, %1; cvt.u32.u64 %0, t; }" : "=r"(a) : "l"(p));
    return a;
}
__device__ __forceinline__ void ldsm4(uint32_t& r0, uint32_t& r1, uint32_t& r2, uint32_t& r3,
                                      uint32_t addr) {
    asm volatile("ldmatrix.sync.aligned.m8n8.x4.shared.b16 {%0,%1,%2,%3}, [%4];"
                 : "=r"(r0), "=r"(r1), "=r"(r2), "=r"(r3) : "r"(addr));
}
#define MMA16816(c, a0, a1, a2, a3, b0, b1)                                            \
    asm volatile(                                                                      \
        "mma.sync.aligned.m16n8k16.row.col.f32.f16.f16.f32 "                           \
        "{%0,%1,%2,%3}, {%4,%5,%6,%7}, {%8,%9}, {%0,%1,%2,%3};"                        \
        : "+f"((c)[0]), "+f"((c)[1]), "+f"((c)[2]), "+f"((c)[3])                       \
        : "r"(a0), "r"(a1), "r"(a2), "r"(a3), "r"(b0), "r"(b1))
#define CP16(dst, src, pred)                                                           \
    asm volatile("cp.async.cg.shared.global [%0], [%1], 16, %2;"                       \
                 :: "r"(dst), "l"(src), "r"((pred) ? 16 : 0) : "memory")
#define CP_COMMIT() asm volatile("cp.async.commit_group;" ::: "memory")
#define CP_WAIT(n)  asm volatile("cp.async.wait_group %0;" :: "n"(n) : "memory")

// ---------------- convert + fused dst histogram + per-block is64 detect ----------------
__global__ void convert_hist_kernel(const void* ei, int twoE) {
    __shared__ int s_is64;
    const int* p32c = (const int*)ei;
    if (threadIdx.x < 32) {
        int nz = 0;
        for (int i = threadIdx.x; i < 256; i += 32)
            if (2 * i + 1 < twoE) nz += (p32c[2 * i + 1] != 0);
        #pragma unroll
        for (int o = 16; o; o >>= 1) nz += __shfl_xor_sync(0xffffffffu, nz, o);
        if (threadIdx.x == 0) s_is64 = (nz == 0);
    }
    __syncthreads();
    int is64 = s_is64;
    int E = twoE / 2;
    const long long* p64 = (const long long*)ei;
    const int* p32 = (const int*)ei;
    for (int i = blockIdx.x * blockDim.x + threadIdx.x; i < twoE; i += gridDim.x * blockDim.x) {
        int v = is64 ? (int)p64[i] : p32[i];
        g_ei[i] = v;
        if (i >= E) atomicAdd(&g_cnt[v], 1);
    }
}

// ---------------- small zero (cnt/fc only; t/rr zeroed in aggregate) ----------------
__global__ void zero_small_kernel(int N) {
    int i = blockIdx.x * blockDim.x + threadIdx.x;
    if (i < N) { g_cnt[i] = 0; g_fc[i] = 0; }
}

// ---------------- CSR build: scan (block-partial) -> fill (blocksum folded in) ----------------
#define SCAN_T 256
#define SCAN_E 1024
__global__ void scan1_kernel(int N) {
    __shared__ int ts[SCAN_T];
    int b = blockIdx.x, t = threadIdx.x;
    int base = b * SCAN_E + t * 4;
    int v[4];
    #pragma unroll
    for (int j = 0; j < 4; j++) v[j] = (base + j < N) ? g_cnt[base + j] : 0;
    int s = v[0] + v[1] + v[2] + v[3];
    ts[t] = s;
    __syncthreads();
    for (int o = 1; o < SCAN_T; o <<= 1) {
        int xv = (t >= o) ? ts[t - o] : 0;
        __syncthreads();
        ts[t] += xv;
        __syncthreads();
    }
    if (t == SCAN_T - 1) g_blocksum[b] = ts[t];
    int run = ts[t] - s;   // exclusive within block
    #pragma unroll
    for (int j = 0; j < 4; j++) {
        if (base + j < N) g_rowstart[base + j] = run;
        run += v[j];
    }
}
__global__ void scan2_kernel(int nb) {
    __shared__ int ts[256];
    int t = threadIdx.x;
    ts[t] = (t < nb) ? g_blocksum[t] : 0;
    __syncthreads();
    int s = ts[t];
    for (int o = 1; o < 256; o <<= 1) {
        int xv = (t >= o) ? ts[t - o] : 0;
        __syncthreads();
        ts[t] += xv;
        __syncthreads();
    }
    g_blocksum[t] = ts[t] - s;   // exclusive block offsets
}
// final rowstart(i) = g_rowstart[i] + g_blocksum[i >> 10]
__global__ void fill_kernel(int E) {
    int e = blockIdx.x * blockDim.x + threadIdx.x;
    if (e >= E) return;
    int s = g_ei[e], d = g_ei[E + e];
    int pos = g_rowstart[d] + g_blocksum[d >> 10] + atomicAdd(&g_fc[d], 1);
    g_csr[pos] = s;
}

// ---------------- layer-1 aggregation + fp16 A materialization + t/rr zero ----------------
__global__ void aggregate_kernel(const float* __restrict__ x, int N, int E) {
    int warp = (blockIdx.x * blockDim.x + threadIdx.x) >> 5;
    int lane = threadIdx.x & 31;
    if (warp >= N) return;
    int start = g_rowstart[warp] + g_blocksum[warp >> 10];
    int end = (warp + 1 < N) ? g_rowstart[warp + 1] + g_blocksum[(warp + 1) >> 10] : E;
    float acc[6] = {0.f, 0.f, 0.f, 0.f, 0.f, 0.f};
    int j = start;
    for (; j + 1 < end; j += 2) {           // 2-neighbor unroll for load MLP
        int s0 = g_csr[j], s1 = g_csr[j + 1];
        const float* xs0 = x + (size_t)s0 * F_IN_;
        const float* xs1 = x + (size_t)s1 * F_IN_;
        #pragma unroll
        for (int m = 0; m < 6; m++) {
            int k = lane + 32 * m;
            if (k < F_IN_) acc[m] += xs0[k] + xs1[k];
        }
    }
    if (j < end) {
        int s = g_csr[j];
        const float* xs = x + (size_t)s * F_IN_;
        #pragma unroll
        for (int m = 0; m < 6; m++) {
            int k = lane + 32 * m;
            if (k < F_IN_) acc[m] += xs[k];
        }
    }
    float inv = 1.0f / fmaxf((float)(end - start), 1.0f);
    __half* ar = g_Ah + (size_t)warp * KPAD;
    const float* xr = x + (size_t)warp * F_IN_;
    #pragma unroll
    for (int m = 0; m < 6; m++) {
        int k = lane + 32 * m;
        if (k < F_IN_) {
            ar[k] = __float2half(acc[m] * inv);
            ar[F_IN_ + k] = __float2half(xr[k]);
        }
    }
    if (lane < KPAD - KTOT) ar[KTOT + lane] = __float2half(0.f);
    if (lane == 0) {
        g_deg[warp] = inv;
        float2 z = make_float2(0.f, 0.f);
        *(float2*)&g_t[2 * warp]  = z;
        *(float2*)&g_rr[2 * warp] = z;
    }
}

// ---------------- B fp16 prep ----------------
__global__ void prep_B_kernel(const float* __restrict__ w1l, const float* __restrict__ w1r) {
    int u = blockIdx.x * blockDim.x + threadIdx.x;
    if (u >= HID_ * (KPAD / 8)) return;
    int n = u / (KPAD / 8);
    int kb = (u % (KPAD / 8)) * 8;
    __align__(16) __half h[8];
    #pragma unroll
    for (int j = 0; j < 8; j++) {
        int k = kb + j;
        float v = 0.f;
        if (k < F_IN_)      v = w1l[k * HID_ + n];
        else if (k < KTOT)  v = w1r[(k - F_IN_) * HID_ + n];
        h[j] = __float2half(v);
    }
    *(uint4*)(g_Bh + (size_t)n * KPAD + kb) = *(const uint4*)h;
}

// ---------------- fp16 mma.sync GEMM: 64x256, 8 warps, 2 CTAs/SM, 3-stage single-sync (R14) ----------------
#define BM     64
#define ROWB   80
#define SA_SZ  (BM * ROWB)            // 5120
#define SB_SZ  (256 * ROWB)           // 20480
#define STG_SZ (SA_SZ + SB_SZ)        // 25600
#define OFF_A(st) ((st) * STG_SZ)
#define OFF_B(st) ((st) * STG_SZ + SA_SZ)
#define OFF_TAB   (3 * STG_SZ)        // 76800
#define SMEM_DYN  (OFF_TAB + 1024 + 2048 + 2048)   // 81920 (x2 CTAs = 160KB/SM, fits)

__global__ __launch_bounds__(256, 2) void gemm_tc_kernel(
    const float* __restrict__ b1, const float* __restrict__ w2l,
    const float* __restrict__ w2r, int N)
{
    extern __shared__ __align__(16) char sm[];
    uint32_t sb = smem_u32(sm);
    float* b1s  = (float*)(sm + OFF_TAB);
    float* w2ls = (float*)(sm + OFF_TAB + 1024);
    float* w2rs = (float*)(sm + OFF_TAB + 1024 + 2048);

    const int tid  = threadIdx.x;
    const int wid  = tid >> 5;
    const int lane = tid & 31;
    const int wm   = wid >> 2;          // 0..1 (32 rows each)
    const int wn   = wid & 3;           // 0..3 (64 cols each)
    const size_t rowbase = (size_t)blockIdx.x * BM;

    for (int i = tid; i < HID_; i += 256) b1s[i] = b1[i];
    for (int i = tid; i < HID_ * 2; i += 256) { w2ls[i] = w2l[i]; w2rs[i] = w2r[i]; }

    float acc[2][8][4];
    #pragma unroll
    for (int a = 0; a < 2; a++)
        #pragma unroll
        for (int b = 0; b < 8; b++)
            #pragma unroll
            for (int c = 0; c < 4; c++) acc[a][b][c] = 0.f;

    auto load_stage = [&](int kt, int buf) {
        {
            int r = tid >> 2, u = tid & 3;
            uint32_t so = sb + OFF_A(buf) + r * ROWB + u * 16;
            size_t row = rowbase + r;
            CP16(so, g_Ah + row * KPAD + kt * BK + u * 8, row < (size_t)N);
        }
        #pragma unroll
        for (int j = 0; j < 4; j++) {
            int cid = tid + 256 * j;
            int r = cid >> 2, u = cid & 3;
            uint32_t so = sb + OFF_B(buf) + r * ROWB + u * 16;
            CP16(so, g_Bh + (size_t)r * KPAD + kt * BK + u * 8, 1);
        }
        CP_COMMIT();
    };

    load_stage(0, 0);
    load_stage(1, 1);

    for (int kt = 0; kt < NITER; kt++) {
        int buf = kt % 3;
        if (kt == NITER - 1) CP_WAIT(0); else CP_WAIT(1);
        __syncthreads();
        if (kt + 2 < NITER) load_stage(kt + 2, (kt + 2) % 3);

        uint32_t sA = sb + OFF_A(buf);
        uint32_t sB = sb + OFF_B(buf);
        #pragma unroll
        for (int ks = 0; ks < 2; ks++) {
            uint32_t bh[4][4];
            #pragma unroll
            for (int nf = 0; nf < 4; nf++) {
                int brow  = wn * 64 + nf * 16 + (lane & 7) + ((lane >> 4) << 3);
                int bunit = ks * 2 + ((lane >> 3) & 1);
                ldsm4(bh[nf][0], bh[nf][1], bh[nf][2], bh[nf][3],
                      sB + brow * ROWB + bunit * 16);
            }
            #pragma unroll
            for (int mf = 0; mf < 2; mf++) {
                int arow  = wm * 32 + mf * 16 + (lane & 15);
                int aunit = ks * 2 + (lane >> 4);
                uint32_t ah0, ah1, ah2, ah3;
                ldsm4(ah0, ah1, ah2, ah3, sA + arow * ROWB + aunit * 16);
                #pragma unroll
                for (int nf8 = 0; nf8 < 8; nf8++) {
                    int nf = nf8 >> 1, hf = nf8 & 1;
                    MMA16816(acc[mf][nf8], ah0, ah1, ah2, ah3,
                             bh[nf][hf * 2], bh[nf][hf * 2 + 1]);
                }
            }
        }
    }

    // ---- fused epilogue: relu(acc+b1) then partial dot with w2l/w2r ----
    float pt0[4], pt1[4], pr0[4], pr1[4];
    #pragma unroll
    for (int i = 0; i < 4; i++) { pt0[i] = pt1[i] = pr0[i] = pr1[i] = 0.f; }

    #pragma unroll
    for (int mf = 0; mf < 2; mf++) {
        #pragma unroll
        for (int nf8 = 0; nf8 < 8; nf8++) {
            #pragma unroll
            for (int j = 0; j < 4; j++) {
                int colL = wn * 64 + nf8 * 8 + 2 * (lane & 3) + (j & 1);
                int i4 = mf * 2 + (j >> 1);
                float h = fmaxf(acc[mf][nf8][j] + b1s[colL], 0.f);
                pt0[i4] += h * w2ls[colL * 2];
                pt1[i4] += h * w2ls[colL * 2 + 1];
                pr0[i4] += h * w2rs[colL * 2];
                pr1[i4] += h * w2rs[colL * 2 + 1];
            }
        }
    }
    #pragma unroll
    for (int i = 0; i < 4; i++) {
        #pragma unroll
        for (int o = 1; o <= 2; o <<= 1) {
            pt0[i] += __shfl_xor_sync(0xffffffffu, pt0[i], o);
            pt1[i] += __shfl_xor_sync(0xffffffffu, pt1[i], o);
            pr0[i] += __shfl_xor_sync(0xffffffffu, pr0[i], o);
            pr1[i] += __shfl_xor_sync(0xffffffffu, pr1[i], o);
        }
        if ((lane & 3) == 0) {
            size_t row = rowbase + wm * 32 + (i >> 1) * 16 + (lane >> 2) + (i & 1) * 8;
            if (row < (size_t)N) {
                asm volatile("red.global.add.v2.f32 [%0], {%1, %2};"
                             :: "l"(&g_t[row * 2]), "f"(pt0[i]), "f"(pt1[i]) : "memory");
                asm volatile("red.global.add.v2.f32 [%0], {%1, %2};"
                             :: "l"(&g_rr[row * 2]), "f"(pr0[i]), "f"(pr1[i]) : "memory");
            }
        }
    }
}

// ---------------- layer-2 gather (CSR, thread-per-node) fused with finalize ----------------
__global__ void gather2_kernel(float* __restrict__ out, const float* __restrict__ b2,
                               int N, int E) {
    int i = blockIdx.x * blockDim.x + threadIdx.x;
    if (i >= N) return;
    int start = g_rowstart[i] + g_blocksum[i >> 10];
    int end = (i + 1 < N) ? g_rowstart[i + 1] + g_blocksum[(i + 1) >> 10] : E;
    float s0 = 0.f, s1 = 0.f;
    for (int j = start; j < end; j++) {
        int s = g_csr[j];
        float2 v = *(const float2*)&g_t[s * 2];
        s0 += v.x;
        s1 += v.y;
    }
    float inv = g_deg[i];
    out[i * 2]     = s0 * inv + g_rr[i * 2]     + __ldg(&b2[0]);
    out[i * 2 + 1] = s1 * inv + g_rr[i * 2 + 1] + __ldg(&b2[1]);
}

// ---------------- edge_index passthrough ----------------
__global__ void ei_out_f32_kernel(float* out, int twoE) {
    int i = blockIdx.x * blockDim.x + threadIdx.x;
    if (i < twoE) out[i] = (float)g_ei[i];
}
__global__ void ei_out_i64_kernel(long long* out, int twoE) {
    int i = blockIdx.x * blockDim.x + threadIdx.x;
    if (i < twoE) out[i] = (long long)g_ei[i];
}

// ---------------- launch ----------------
extern "C" void kernel_launch(void* const* d_in, const int* in_sizes, int n_in,
                              void* d_out, int out_size) {
    const float* x   = (const float*)d_in[0];
    const void*  ei  = d_in[1];
    const float* w1l = (const float*)d_in[2];
    const float* w1r = (const float*)d_in[3];
    const float* b1  = (const float*)d_in[4];
    const float* w2l = (const float*)d_in[5];
    const float* w2r = (const float*)d_in[6];
    const float* b2  = (const float*)d_in[7];

    int N = in_sizes[0] / F_IN_;
    int twoE = in_sizes[1];
    int E = twoE / 2;
    float* out = (float*)d_out;

    cudaFuncSetAttribute(gemm_tc_kernel, cudaFuncAttributeMaxDynamicSharedMemorySize, SMEM_DYN);

    zero_small_kernel<<<(N + 255) / 256, 256>>>(N);
    convert_hist_kernel<<<1024, 256>>>(ei, twoE);
    int nsb = (N + SCAN_E - 1) / SCAN_E;
    scan1_kernel<<<nsb, SCAN_T>>>(N);
    scan2_kernel<<<1, 256>>>(nsb);
    fill_kernel<<<(E + 255) / 256, 256>>>(E);
    aggregate_kernel<<<(N * 32 + 255) / 256, 256>>>(x, N, E);
    prep_B_kernel<<<(HID_ * (KPAD / 8) + 255) / 256, 256>>>(w1l, w1r);
    gemm_tc_kernel<<<(N + BM - 1) / BM, 256, SMEM_DYN>>>(b1, w2l, w2r, N);
    gather2_kernel<<<(N + 255) / 256, 256>>>(out, b2, N, E);

    long long rem = (long long)out_size - (long long)2 * N;
    if (rem >= (long long)twoE) {
        if (rem >= 2LL * twoE)
            ei_out_i64_kernel<<<(twoE + 255) / 256, 256>>>((long long*)(out + (size_t)2 * N), twoE);
        else
            ei_out_f32_kernel<<<(twoE + 255) / 256, 256>>>(out + (size_t)2 * N, twoE);
    }
}